// round 2
// baseline (speedup 1.0000x reference)
#include <cuda_runtime.h>
#include <cstdint>

// out = self_tensor; out[sorted_index[i], :] += value[i, :]
// N=262144 rows, M=1048576 updates, D=128 cols, fp32. sorted_index is SORTED.
// NOTE: harness delivers int64 tensors as int32 — read idx as const int*.
//
// One warp per OUTPUT row r. Contributions to row r are the contiguous run
// [lower_bound(idx, r), lower_bound(idx, r+1)) in `value`. Lanes 0 and 1 each
// run one binary search in lockstep, broadcast via shfl, then all 32 lanes
// stream the run with float4 loads (lane c owns columns 4c..4c+3) and write
// once. Zero atomics; every DRAM byte touched exactly once, fully coalesced.

static constexpr int D4 = 32;  // 128 floats = 32 float4 per row

__global__ void scatter_add_rows_kernel(const float* __restrict__ self_t,
                                        const float* __restrict__ value,
                                        const int* __restrict__ idx,
                                        float* __restrict__ out,
                                        int n_rows, int m) {
    const int warp = (blockIdx.x * blockDim.x + threadIdx.x) >> 5;
    const int lane = threadIdx.x & 31;
    if (warp >= n_rows) return;

    const int r = warp;

    // lanes 0,1 do lower_bound(idx, r) and lower_bound(idx, r+1) in lockstep
    int lo = 0;
    if (lane < 2) {
        const int target = r + lane;
        int hi = m;
        while (lo < hi) {
            int mid = (lo + hi) >> 1;
            if (__ldg(&idx[mid]) < target) lo = mid + 1;
            else                           hi = mid;
        }
    }
    const int start = __shfl_sync(0xffffffffu, lo, 0);
    const int end   = __shfl_sync(0xffffffffu, lo, 1);

    const float4* __restrict__ selfv = reinterpret_cast<const float4*>(self_t);
    const float4* __restrict__ valv  = reinterpret_cast<const float4*>(value);
    float4* __restrict__ outv        = reinterpret_cast<float4*>(out);

    float4 acc = __ldg(&selfv[(size_t)r * D4 + lane]);

    const float4* p = valv + (size_t)start * D4 + lane;
    for (int i = start; i < end; ++i) {
        float4 v = __ldg(p);
        acc.x += v.x; acc.y += v.y; acc.z += v.z; acc.w += v.w;
        p += D4;
    }

    outv[(size_t)r * D4 + lane] = acc;
}

extern "C" void kernel_launch(void* const* d_in, const int* in_sizes, int n_in,
                              void* d_out, int out_size) {
    const float* self_t = (const float*)d_in[0];  // (N, 128) fp32
    const float* value  = (const float*)d_in[1];  // (M, 128) fp32
    const int*   idx    = (const int*)d_in[2];    // (M,) sorted (int64->int32)
    // d_in[3] = pos, unused

    const int m      = in_sizes[2];       // 1048576
    const int n_rows = out_size / 128;    // 262144

    const int threads = 256;              // 8 warps/block
    const int blocks = (n_rows * 32 + threads - 1) / threads;

    scatter_add_rows_kernel<<<blocks, threads>>>(self_t, value, idx,
                                                 (float*)d_out, n_rows, m);
}

// round 3
// speedup vs baseline: 1.6155x; 1.6155x over previous
#include <cuda_runtime.h>
#include <cstdint>

// out = self_tensor; out[sorted_index[i], :] += value[i, :]
// N=262144 rows, M=1048576 updates, D=128 cols, fp32. sorted_index SORTED,
// delivered as int32 by the harness.
//
// Pass 1 (cheap): build CSR row-start offsets from the sorted index —
//   starts[r] = lower_bound(idx, r), starts[N] = M — one parallel pass,
//   thread i fills starts[r] for r in (idx[i-1], idx[i]].
// Pass 2: one warp per output row; reads starts[r], starts[r+1] (2 coalesced
//   L1-hit loads instead of a 20-deep dependent binary-search chain), streams
//   the run of value rows with float4, writes once. No atomics; every DRAM
//   byte of the 776MB footprint touched exactly once, evict-first hinted.

static constexpr int D4 = 32;          // 128 floats = 32 float4/row
static constexpr int MAX_ROWS = 262144;

__device__ int g_starts[MAX_ROWS + 1];

__global__ void build_starts_kernel(const int* __restrict__ idx,
                                    int m, int n_rows) {
    int i = blockIdx.x * blockDim.x + threadIdx.x;
    if (i > m) return;
    int b = (i < m) ? __ldg(&idx[i]) : n_rows;        // virtual idx[m] = n
    int a = (i > 0) ? __ldg(&idx[i - 1]) : -1;
    for (int r = a + 1; r <= b; ++r) g_starts[r] = i;
}

__global__ void scatter_add_rows_kernel(const float* __restrict__ self_t,
                                        const float* __restrict__ value,
                                        float* __restrict__ out,
                                        int n_rows) {
    const int warp = (blockIdx.x * blockDim.x + threadIdx.x) >> 5;
    const int lane = threadIdx.x & 31;
    if (warp >= n_rows) return;

    const int r = warp;

    int s = 0;
    if (lane < 2) s = g_starts[r + lane];
    const int start = __shfl_sync(0xffffffffu, s, 0);
    const int end   = __shfl_sync(0xffffffffu, s, 1);

    const float4* __restrict__ selfv = reinterpret_cast<const float4*>(self_t);
    const float4* __restrict__ valv  = reinterpret_cast<const float4*>(value);
    float4* __restrict__ outv        = reinterpret_cast<float4*>(out);

    float4 acc = __ldcs(&selfv[(size_t)r * D4 + lane]);

    const float4* p = valv + (size_t)start * D4 + lane;
    int n = end - start;
    // unroll by 2 for MLP on the streamed loads
    for (; n >= 2; n -= 2) {
        float4 v0 = __ldcs(p);
        float4 v1 = __ldcs(p + D4);
        acc.x += v0.x; acc.y += v0.y; acc.z += v0.z; acc.w += v0.w;
        acc.x += v1.x; acc.y += v1.y; acc.z += v1.z; acc.w += v1.w;
        p += 2 * D4;
    }
    if (n) {
        float4 v = __ldcs(p);
        acc.x += v.x; acc.y += v.y; acc.z += v.z; acc.w += v.w;
    }

    __stcs(&outv[(size_t)r * D4 + lane], acc);
}

extern "C" void kernel_launch(void* const* d_in, const int* in_sizes, int n_in,
                              void* d_out, int out_size) {
    const float* self_t = (const float*)d_in[0];  // (N, 128) fp32
    const float* value  = (const float*)d_in[1];  // (M, 128) fp32
    const int*   idx    = (const int*)d_in[2];    // (M,) sorted
    // d_in[3] = pos, unused

    const int m      = in_sizes[2];       // 1048576
    const int n_rows = out_size / 128;    // 262144 (<= MAX_ROWS)

    {
        const int threads = 256;
        const int blocks = (m + 1 + threads - 1) / threads;
        build_starts_kernel<<<blocks, threads>>>(idx, m, n_rows);
    }
    {
        const int threads = 256;          // 8 warps/block
        const int blocks = (n_rows * 32 + threads - 1) / threads;
        scatter_add_rows_kernel<<<blocks, threads>>>(self_t, value,
                                                     (float*)d_out, n_rows);
    }
}

// round 4
// speedup vs baseline: 1.6372x; 1.0134x over previous
#include <cuda_runtime.h>
#include <cstdint>

// out = self_tensor; out[sorted_index[i], :] += value[i, :]
// N=262144 rows, M=1048576 updates, D=128 cols, fp32. sorted_index SORTED,
// delivered as int32 by the harness.
//
// Pass 1: CSR row-start offsets from the sorted index (starts[r] =
//   lower_bound(idx, r), starts[N] = M). ~5MB of traffic.
// Pass 2: one warp per output row; 2 coalesced L1-hit loads of starts,
//   then stream the run of value rows with 4-deep batched float4 loads
//   (MLP=4) and a single store. No atomics; every DRAM byte of the 776MB
//   footprint touched exactly once, evict-first hinted so idx/starts stay
//   L2-resident.

static constexpr int D4 = 32;          // 128 floats = 32 float4/row
static constexpr int MAX_ROWS = 262144;

__device__ int g_starts[MAX_ROWS + 1];

__global__ void build_starts_kernel(const int* __restrict__ idx,
                                    int m, int n_rows) {
    int i = blockIdx.x * blockDim.x + threadIdx.x;
    if (i > m) return;
    int b = (i < m) ? __ldg(&idx[i]) : n_rows;        // virtual idx[m] = n
    int a = (i > 0) ? __ldg(&idx[i - 1]) : -1;
    for (int r = a + 1; r <= b; ++r) g_starts[r] = i;
}

__global__ void scatter_add_rows_kernel(const float* __restrict__ self_t,
                                        const float* __restrict__ value,
                                        float* __restrict__ out,
                                        int n_rows) {
    const int warp = (blockIdx.x * blockDim.x + threadIdx.x) >> 5;
    const int lane = threadIdx.x & 31;
    if (warp >= n_rows) return;

    const int r = warp;

    const float4* __restrict__ selfv = reinterpret_cast<const float4*>(self_t);
    const float4* __restrict__ valv  = reinterpret_cast<const float4*>(value);
    float4* __restrict__ outv        = reinterpret_cast<float4*>(out);

    // issue the self load early; overlap with starts lookup
    float4 acc = __ldcs(&selfv[(size_t)r * D4 + lane]);

    int s = 0;
    if (lane < 2) s = g_starts[r + lane];
    const int start = __shfl_sync(0xffffffffu, s, 0);
    const int end   = __shfl_sync(0xffffffffu, s, 1);

    const float4* p = valv + (size_t)start * D4 + lane;
    int n = end - start;

    // 4-deep batched loads: 4 independent LDG.128 in flight per iteration
    while (n >= 4) {
        float4 v0 = __ldcs(p);
        float4 v1 = __ldcs(p + D4);
        float4 v2 = __ldcs(p + 2 * D4);
        float4 v3 = __ldcs(p + 3 * D4);
        acc.x += v0.x; acc.y += v0.y; acc.z += v0.z; acc.w += v0.w;
        acc.x += v1.x; acc.y += v1.y; acc.z += v1.z; acc.w += v1.w;
        acc.x += v2.x; acc.y += v2.y; acc.z += v2.z; acc.w += v2.w;
        acc.x += v3.x; acc.y += v3.y; acc.z += v3.z; acc.w += v3.w;
        p += 4 * D4;
        n -= 4;
    }
    if (n >= 2) {
        float4 v0 = __ldcs(p);
        float4 v1 = __ldcs(p + D4);
        acc.x += v0.x; acc.y += v0.y; acc.z += v0.z; acc.w += v0.w;
        acc.x += v1.x; acc.y += v1.y; acc.z += v1.z; acc.w += v1.w;
        p += 2 * D4;
        n -= 2;
    }
    if (n) {
        float4 v = __ldcs(p);
        acc.x += v.x; acc.y += v.y; acc.z += v.z; acc.w += v.w;
    }

    __stcs(&outv[(size_t)r * D4 + lane], acc);
}

extern "C" void kernel_launch(void* const* d_in, const int* in_sizes, int n_in,
                              void* d_out, int out_size) {
    const float* self_t = (const float*)d_in[0];  // (N, 128) fp32
    const float* value  = (const float*)d_in[1];  // (M, 128) fp32
    const int*   idx    = (const int*)d_in[2];    // (M,) sorted
    // d_in[3] = pos, unused

    const int m      = in_sizes[2];       // 1048576
    const int n_rows = out_size / 128;    // 262144 (<= MAX_ROWS)

    {
        const int threads = 512;
        const int blocks = (m + 1 + threads - 1) / threads;
        build_starts_kernel<<<blocks, threads>>>(idx, m, n_rows);
    }
    {
        const int threads = 256;          // 8 warps/block
        const int blocks = (n_rows * 32 + threads - 1) / threads;
        scatter_add_rows_kernel<<<blocks, threads>>>(self_t, value,
                                                     (float*)d_out, n_rows);
    }
}